// round 14
// baseline (speedup 1.0000x reference)
#include <cuda_runtime.h>

#define NN 512
#define NB 16
#define MU 768
#define GRID 740          // 148 SMs x 5 resident CTAs -> one persistent wave

__device__ float2 g_A1[NB * NN * NN];   // row-FFT, only kx<=256 valid  [b][y][kx]
__device__ float2 g_A2[NB * NN * NN];   // half spectrum, kx<=256      [b][kx][ky]
__device__ float2 g_W[64];              // forward twiddles e^{-2pi i r/512}, r<64

__device__ __forceinline__ float2 cadd(float2 a, float2 b) { return make_float2(a.x + b.x, a.y + b.y); }
__device__ __forceinline__ float2 csub(float2 a, float2 b) { return make_float2(a.x - b.x, a.y - b.y); }
__device__ __forceinline__ float2 cmul(float2 a, float2 b) {
    return make_float2(a.x * b.x - a.y * b.y, a.x * b.y + a.y * b.x);
}

// bank-conflict-killing swizzle: XOR bits[4:6] into bits[1:3] (involution)
__device__ __forceinline__ int swz(int i) { return i ^ (((i >> 4) & 7) << 1); }

// barrier shared by a PAIR of 64-thread FFT units (128 threads), id in {1,2}
__device__ __forceinline__ void bar128(int id) {
    asm volatile("bar.sync %0, 128;" :: "r"(id) : "memory");
}

template <bool CONJ>
__device__ __forceinline__ void dft8(const float2 a[8], float2 b[8]) {
    const float C = 0.70710678118654752f;
    float2 u0 = cadd(a[0], a[4]), u1 = cadd(a[1], a[5]);
    float2 u2 = cadd(a[2], a[6]), u3 = cadd(a[3], a[7]);
    float2 v0 = csub(a[0], a[4]);
    float2 d1 = csub(a[1], a[5]);
    float2 d2 = csub(a[2], a[6]);
    float2 d3 = csub(a[3], a[7]);
    float2 v1, v2, v3;
    if (!CONJ) {
        v1 = make_float2(C * (d1.x + d1.y), C * (d1.y - d1.x));
        v2 = make_float2(d2.y, -d2.x);
        v3 = make_float2(C * (d3.y - d3.x), -C * (d3.x + d3.y));
    } else {
        v1 = make_float2(C * (d1.x - d1.y), C * (d1.x + d1.y));
        v2 = make_float2(-d2.y, d2.x);
        v3 = make_float2(-C * (d3.x + d3.y), C * (d3.x - d3.y));
    }
    {
        float2 x0 = cadd(u0, u2), x1 = cadd(u1, u3);
        float2 y0 = csub(u0, u2);
        float2 t = csub(u1, u3);
        float2 y1 = (!CONJ) ? make_float2(t.y, -t.x) : make_float2(-t.y, t.x);
        b[0] = cadd(x0, x1); b[4] = csub(x0, x1);
        b[2] = cadd(y0, y1); b[6] = csub(y0, y1);
    }
    {
        float2 x0 = cadd(v0, v2), x1 = cadd(v1, v3);
        float2 y0 = csub(v0, v2);
        float2 t = csub(v1, v3);
        float2 y1 = (!CONJ) ? make_float2(t.y, -t.x) : make_float2(-t.y, t.x);
        b[1] = cadd(x0, x1); b[5] = csub(x0, x1);
        b[3] = cadd(y0, y1); b[7] = csub(y0, y1);
    }
}

template <bool CONJ, int M>
__device__ __forceinline__ void do_stage(const float2* src, float2* dst,
                                         const float2* W, int p) {
    float2 a[8];
#pragma unroll
    for (int r = 0; r < 8; r++) a[r] = src[swz(p + 64 * r)];
    float2 b[8];
    dft8<CONJ>(a, b);
    if (M == 64) {
#pragma unroll
        for (int q = 0; q < 8; q++) dst[swz(p + 64 * q)] = b[q];
    } else {
        const int k = p & (M - 1);
        const int jm = p - k;              // always < 64
        float2 w1 = W[jm];
        if (CONJ) w1.y = -w1.y;
        float2 w2 = cmul(w1, w1);
        float2 w3 = cmul(w2, w1);
        float2 w4 = cmul(w2, w2);
        float2 w5 = cmul(w4, w1);
        float2 w6 = cmul(w4, w2);
        float2 w7 = cmul(w4, w3);
        const int base = 8 * jm + k;
        dst[swz(base)]         = b[0];
        dst[swz(base + M)]     = cmul(b[1], w1);
        dst[swz(base + 2 * M)] = cmul(b[2], w2);
        dst[swz(base + 3 * M)] = cmul(b[3], w3);
        dst[swz(base + 4 * M)] = cmul(b[4], w4);
        dst[swz(base + 5 * M)] = cmul(b[5], w5);
        dst[swz(base + 6 * M)] = cmul(b[6], w6);
        dst[swz(base + 7 * M)] = cmul(b[7], w7);
    }
}

// 512-pt FFT: 3 radix-8 stages; barrier shared by unit pair (bid = 1 + f/2).
template <bool CONJ>
__device__ __forceinline__ void run_fft(float2* bufA, float2* bufB,
                                        const float2* W, int p, int bid) {
    do_stage<CONJ, 1>(bufA, bufB, W, p);
    bar128(bid);
    do_stage<CONJ, 8>(bufB, bufA, W, p);
    bar128(bid);
    do_stage<CONJ, 64>(bufA, bufB, W, p);
    bar128(bid);
}

__global__ void twiddle_init() {
    const int r = threadIdx.x;
    float s, c;
    sincosf(-6.283185307179586f * (float)r * (1.0f / 512.0f), &s, &c);
    g_W[r] = make_float2(c, s);
}

__device__ __forceinline__ void load_tw(float2* sW, int tid) {
    if (tid < 64) sW[tid] = g_W[tid];
}

// Stage A: forward FFT along x for PAIRS of real rows (Z = rowA + i*rowB).
// Persistent: item = (b, y-group of 8). 4 units = 8 rows per item.
__global__ __launch_bounds__(256, 5) void fft_rows(const float* __restrict__ img) {
    __shared__ float2 sA[4 * 512], sB[4 * 512], sW[64];
    const int tid = threadIdx.x, f = tid >> 6, p = tid & 63;
    load_tw(sW, tid);
    for (int it = blockIdx.x; it < 64 * NB; it += GRID) {
        const int b = it & 15, y0 = (it >> 4) * 8;
        const float* src = img + ((size_t)b * NN + y0) * NN;
        for (int i = tid; i < 4 * 512; i += 256) {
            const int ff = i >> 9, x = i & 511;
            sA[ff * 512 + swz(x)] =
                make_float2(__ldcs(&src[(2 * ff) * NN + x]),
                            __ldcs(&src[(2 * ff + 1) * NN + x]));
        }
        __syncthreads();
        run_fft<false>(sA + f * 512, sB + f * 512, sW, p, 1 + (f >> 1));
        float2* dst = g_A1 + ((size_t)b * NN + y0) * NN;
        // Hermitian untangle: X = (Z[k]+conj(Z[-k]))/2 ; Y = -i(Z[k]-conj(Z[-k]))/2
#pragma unroll
        for (int k = p; k < 257; k += 64) {
            const float2 Zr = sB[f * 512 + swz(k)];
            const float2 Zs = sB[f * 512 + swz((512 - k) & 511)];
            dst[(2 * f) * NN + k] =
                make_float2(0.5f * (Zr.x + Zs.x), 0.5f * (Zr.y - Zs.y));
            dst[(2 * f + 1) * NN + k] =
                make_float2(0.5f * (Zr.y + Zs.y), 0.5f * (Zs.x - Zr.x));
        }
        __syncthreads();      // sB fully consumed before next item overwrites sA/sB
    }
}

// Stage B: forward FFT along y for kx in [0,256]; store A2[kx][ky].
// Persistent: item = (b, kx-group of 4).
__global__ __launch_bounds__(256, 5) void fft_cols() {
    __shared__ float2 sA[4 * 512], sB[4 * 512], sW[64];
    const int tid = threadIdx.x, f = tid >> 6, p = tid & 63;
    load_tw(sW, tid);
    for (int it = blockIdx.x; it < 65 * NB; it += GRID) {
        const int b = it & 15, kx0 = (it >> 4) * 4;
        const float2* src = g_A1 + (size_t)b * NN * NN;
        for (int i = tid; i < 4 * 512; i += 256) {
            const int c = i & 3, y = i >> 2;    // 4 consecutive lanes share a sector
            sA[c * 512 + swz(y)] = src[(size_t)y * NN + kx0 + c];
        }
        __syncthreads();
        run_fft<false>(sA + f * 512, sB + f * 512, sW, p, 1 + (f >> 1));
        const int kx = kx0 + f;
        if (kx <= 256) {
            float2* dst = g_A2 + ((size_t)b * NN + kx) * NN;
#pragma unroll
            for (int ky = p; ky < 512; ky += 64) dst[ky] = sB[f * 512 + swz(ky)];
        }
        __syncthreads();
    }
}

// Fetch A2 element with Hermitian mirror for kx > 256.
__device__ __forceinline__ float2 fetch(const float2* A2, int kx, int ky) {
    if (kx <= 256) return A2[kx * NN + ky];
    const float2 v = A2[(NN - kx) * NN + ((NN - ky) & 511)];
    return make_float2(v.x, -v.y);
}

// Stage C: slices Hermitian -> gather only k<=256, mirror-fill in smem.
// Two slices per inverse FFT (Z = s1 + i*s2). Persistent: item = (b, 8 lines).
__global__ __launch_bounds__(256, 5) void gather_ifft(float* __restrict__ out) {
    __shared__ float2 sA[4 * 512], sB[4 * 512], sW[64];
    const int tid = threadIdx.x, f = tid >> 6, p = tid & 63;
    load_tw(sW, tid);
    for (int it = blockIdx.x; it < 96 * NB; it += GRID) {
        const int b = it & 15, base = (it >> 4) * 8;
        const float2* A2 = g_A2 + (size_t)b * NN * NN;
        const int m1 = base + 2 * f, m2 = m1 + 1;
        float2* buf = sA + f * 512;

        if (m1 < NN) {          // family 1: (kx,ky) = (k*m mod 512, k)
            int kx1 = (p * m1) & 511, kx2 = (p * m2) & 511;
            const int d1 = (64 * m1) & 511, d2 = (64 * m2) & 511;
#pragma unroll
            for (int i = 0; i < 4; i++) {
                const int k = p + 64 * i;
                const float2 s1 = fetch(A2, kx1, k);
                const float2 s2 = fetch(A2, kx2, k);
                buf[swz(k)] = make_float2(s1.x - s2.y, s1.y + s2.x);
                if (k > 0)      // mirror: Z[512-k] = conj(s1)+i*conj(s2)
                    buf[swz(512 - k)] = make_float2(s1.x + s2.y, s2.x - s1.y);
                kx1 = (kx1 + d1) & 511;
                kx2 = (kx2 + d2) & 511;
            }
            if (p == 0) {
                const float2 s1 = fetch(A2, (256 * m1) & 511, 256);
                const float2 s2 = fetch(A2, (256 * m2) & 511, 256);
                buf[swz(256)] = make_float2(s1.x - s2.y, s1.y + s2.x);
            }
        } else {                // family 2: (kx,ky) = (k, 2k(m-512) mod 512)
            const int t1 = m1 - NN, t2 = m2 - NN;
            int ky1 = (2 * p * t1) & 511, ky2 = (2 * p * t2) & 511;
            const int e1 = (128 * t1) & 511, e2 = (128 * t2) & 511;
#pragma unroll
            for (int i = 0; i < 4; i++) {
                const int k = p + 64 * i;
                const float2 s1 = A2[k * NN + ky1];
                const float2 s2 = A2[k * NN + ky2];
                buf[swz(k)] = make_float2(s1.x - s2.y, s1.y + s2.x);
                if (k > 0)
                    buf[swz(512 - k)] = make_float2(s1.x + s2.y, s2.x - s1.y);
                ky1 = (ky1 + e1) & 511;
                ky2 = (ky2 + e2) & 511;
            }
            if (p == 0) {
                const float2 s1 = A2[256 * NN + ((512 * t1) & 511)];
                const float2 s2 = A2[256 * NN + ((512 * t2) & 511)];
                buf[swz(256)] = make_float2(s1.x - s2.y, s1.y + s2.x);
            }
        }
        __syncthreads();
        run_fft<true>(sA + f * 512, sB + f * 512, sW, p, 1 + (f >> 1));
        const float SC = 8.6316745750242931e-5f;    // 1 / 512^1.5
        float2* o1 = (float2*)out + ((size_t)b * MU + m1) * NN;
        float2* o2 = (float2*)out + ((size_t)b * MU + m2) * NN;
#pragma unroll
        for (int s = p; s < 512; s += 64) {
            const float2 v = sB[f * 512 + swz(s)];
            __stcs(&o1[s], make_float2(v.x * SC, 0.0f));
            __stcs(&o2[s], make_float2(v.y * SC, 0.0f));
        }
        __syncthreads();
    }
}

extern "C" void kernel_launch(void* const* d_in, const int* in_sizes, int n_in,
                              void* d_out, int out_size) {
    const float* img = (const float*)d_in[0];
    float* out = (float*)d_out;

    twiddle_init<<<1, 64>>>();
    fft_rows<<<GRID, 256>>>(img);
    fft_cols<<<GRID, 256>>>();
    gather_ifft<<<GRID, 256>>>(out);
}

// round 15
// speedup vs baseline: 1.0011x; 1.0011x over previous
#include <cuda_runtime.h>

#define NN 512
#define NB 16
#define MU 768

__device__ float2 g_A1[NB * NN * NN];   // row-FFT, only kx<=256 valid  [b][y][kx]
__device__ float2 g_A2[NB * NN * NN];   // half spectrum, kx<=256      [b][kx][ky]
__device__ float2 g_W[64];              // forward twiddles e^{-2pi i r/512}, r<64

__device__ __forceinline__ float2 cadd(float2 a, float2 b) { return make_float2(a.x + b.x, a.y + b.y); }
__device__ __forceinline__ float2 csub(float2 a, float2 b) { return make_float2(a.x - b.x, a.y - b.y); }
__device__ __forceinline__ float2 cmul(float2 a, float2 b) {
    return make_float2(a.x * b.x - a.y * b.y, a.x * b.y + a.y * b.x);
}

// bank-conflict-killing swizzle: XOR bits[4:6] into bits[1:3] (involution)
__device__ __forceinline__ int swz(int i) { return i ^ (((i >> 4) & 7) << 1); }

// barrier shared by a PAIR of 64-thread FFT units (128 threads), id in {1,2}
__device__ __forceinline__ void bar128(int id) {
    asm volatile("bar.sync %0, 128;" :: "r"(id) : "memory");
}

template <bool CONJ>
__device__ __forceinline__ void dft8(const float2 a[8], float2 b[8]) {
    const float C = 0.70710678118654752f;
    float2 u0 = cadd(a[0], a[4]), u1 = cadd(a[1], a[5]);
    float2 u2 = cadd(a[2], a[6]), u3 = cadd(a[3], a[7]);
    float2 v0 = csub(a[0], a[4]);
    float2 d1 = csub(a[1], a[5]);
    float2 d2 = csub(a[2], a[6]);
    float2 d3 = csub(a[3], a[7]);
    float2 v1, v2, v3;
    if (!CONJ) {
        v1 = make_float2(C * (d1.x + d1.y), C * (d1.y - d1.x));
        v2 = make_float2(d2.y, -d2.x);
        v3 = make_float2(C * (d3.y - d3.x), -C * (d3.x + d3.y));
    } else {
        v1 = make_float2(C * (d1.x - d1.y), C * (d1.x + d1.y));
        v2 = make_float2(-d2.y, d2.x);
        v3 = make_float2(-C * (d3.x + d3.y), C * (d3.x - d3.y));
    }
    {
        float2 x0 = cadd(u0, u2), x1 = cadd(u1, u3);
        float2 y0 = csub(u0, u2);
        float2 t = csub(u1, u3);
        float2 y1 = (!CONJ) ? make_float2(t.y, -t.x) : make_float2(-t.y, t.x);
        b[0] = cadd(x0, x1); b[4] = csub(x0, x1);
        b[2] = cadd(y0, y1); b[6] = csub(y0, y1);
    }
    {
        float2 x0 = cadd(v0, v2), x1 = cadd(v1, v3);
        float2 y0 = csub(v0, v2);
        float2 t = csub(v1, v3);
        float2 y1 = (!CONJ) ? make_float2(t.y, -t.x) : make_float2(-t.y, t.x);
        b[1] = cadd(x0, x1); b[5] = csub(x0, x1);
        b[3] = cadd(y0, y1); b[7] = csub(y0, y1);
    }
}

// In-place radix-8 Stockham stage: read to regs, bar, write permuted, bar.
template <bool CONJ, int M>
__device__ __forceinline__ void stage_ip(float2* buf, const float2* W, int p,
                                         int bid) {
    float2 a[8];
#pragma unroll
    for (int r = 0; r < 8; r++) a[r] = buf[swz(p + 64 * r)];
    bar128(bid);
    float2 b[8];
    dft8<CONJ>(a, b);
    if (M == 64) {
#pragma unroll
        for (int q = 0; q < 8; q++) buf[swz(p + 64 * q)] = b[q];
    } else {
        const int k = p & (M - 1);
        const int jm = p - k;              // always < 64
        float2 w1 = W[jm];
        if (CONJ) w1.y = -w1.y;
        float2 w2 = cmul(w1, w1);
        float2 w3 = cmul(w2, w1);
        float2 w4 = cmul(w2, w2);
        float2 w5 = cmul(w4, w1);
        float2 w6 = cmul(w4, w2);
        float2 w7 = cmul(w4, w3);
        const int base = 8 * jm + k;
        buf[swz(base)]         = b[0];
        buf[swz(base + M)]     = cmul(b[1], w1);
        buf[swz(base + 2 * M)] = cmul(b[2], w2);
        buf[swz(base + 3 * M)] = cmul(b[3], w3);
        buf[swz(base + 4 * M)] = cmul(b[4], w4);
        buf[swz(base + 5 * M)] = cmul(b[5], w5);
        buf[swz(base + 6 * M)] = cmul(b[6], w6);
        buf[swz(base + 7 * M)] = cmul(b[7], w7);
    }
    bar128(bid);
}

// 512-pt FFT, in place in buf. Barrier shared by unit pair (bid = 1 + f/2).
template <bool CONJ>
__device__ __forceinline__ void run_fft(float2* buf, const float2* W, int p,
                                        int bid) {
    stage_ip<CONJ, 1>(buf, W, p, bid);
    stage_ip<CONJ, 8>(buf, W, p, bid);
    stage_ip<CONJ, 64>(buf, W, p, bid);
}

__global__ void twiddle_init() {
    const int r = threadIdx.x;
    float s, c;
    sincosf(-6.283185307179586f * (float)r * (1.0f / 512.0f), &s, &c);
    g_W[r] = make_float2(c, s);
}

__device__ __forceinline__ void load_tw(float2* sW, int tid) {
    if (tid < 64) sW[tid] = g_W[tid];
}

// Stage A: forward FFT along x for PAIRS of real rows (Z = rowA + i*rowB).
// 4 units = 8 rows per CTA. Store only kx in [0,256] of A1.
__global__ __launch_bounds__(256, 5) void fft_rows(const float* __restrict__ img) {
    __shared__ float2 sA[4 * 512], sW[64];
    const int tid = threadIdx.x, f = tid >> 6, p = tid & 63;
    const int y0 = blockIdx.x * 8, b = blockIdx.y;   // 4 pairs = 8 rows per CTA
    load_tw(sW, tid);
    const float* src = img + ((size_t)b * NN + y0) * NN;
    for (int i = tid; i < 4 * 512; i += 256) {
        const int ff = i >> 9, x = i & 511;
        sA[ff * 512 + swz(x)] =
            make_float2(__ldcs(&src[(2 * ff) * NN + x]),
                        __ldcs(&src[(2 * ff + 1) * NN + x]));
    }
    __syncthreads();
    float2* buf = sA + f * 512;
    run_fft<false>(buf, sW, p, 1 + (f >> 1));
    float2* dst = g_A1 + ((size_t)b * NN + y0) * NN;
    // Hermitian untangle: X[k] = (Z[k]+conj(Z[-k]))/2 ; Y[k] = -i(Z[k]-conj(Z[-k]))/2
#pragma unroll
    for (int k = p; k < 257; k += 64) {
        const float2 Zr = buf[swz(k)];
        const float2 Zs = buf[swz((512 - k) & 511)];
        dst[(2 * f) * NN + k] =
            make_float2(0.5f * (Zr.x + Zs.x), 0.5f * (Zr.y - Zs.y));
        dst[(2 * f + 1) * NN + k] =
            make_float2(0.5f * (Zr.y + Zs.y), 0.5f * (Zs.x - Zr.x));
    }
}

// Stage B: forward FFT along y for kx in [0,256] only; store A2[kx][ky].
__global__ __launch_bounds__(256, 5) void fft_cols() {
    __shared__ float2 sA[4 * 512], sW[64];
    const int tid = threadIdx.x, f = tid >> 6, p = tid & 63;
    const int kx0 = blockIdx.x * 4, b = blockIdx.y;
    load_tw(sW, tid);
    const float2* src = g_A1 + (size_t)b * NN * NN;
    for (int i = tid; i < 4 * 512; i += 256) {
        const int c = i & 3, y = i >> 2;        // 4 consecutive lanes share a sector
        sA[c * 512 + swz(y)] = src[(size_t)y * NN + kx0 + c];
    }
    __syncthreads();
    float2* buf = sA + f * 512;
    run_fft<false>(buf, sW, p, 1 + (f >> 1));
    const int kx = kx0 + f;
    if (kx <= 256) {
        float2* dst = g_A2 + ((size_t)b * NN + kx) * NN;
#pragma unroll
        for (int ky = p; ky < 512; ky += 64) dst[ky] = buf[swz(ky)];
    }
}

// Fetch A2 element with Hermitian mirror for kx > 256.
__device__ __forceinline__ float2 fetch(const float2* A2, int kx, int ky) {
    if (kx <= 256) return A2[kx * NN + ky];
    const float2 v = A2[(NN - kx) * NN + ((NN - ky) & 511)];
    return make_float2(v.x, -v.y);
}

// Stage C: slices Hermitian -> gather only k<=256, mirror-fill in smem.
// Two slices per inverse FFT (Z = s1 + i*s2). 4 units = 8 lines per CTA.
__global__ __launch_bounds__(256, 5) void gather_ifft(float* __restrict__ out) {
    __shared__ float2 sA[4 * 512], sW[64];
    const int tid = threadIdx.x, f = tid >> 6, p = tid & 63;
    const int base = blockIdx.x * 8, b = blockIdx.y;   // 4 pairs = 8 lines per CTA
    load_tw(sW, tid);
    const float2* A2 = g_A2 + (size_t)b * NN * NN;
    const int m1 = base + 2 * f, m2 = m1 + 1;
    float2* buf = sA + f * 512;

    if (m1 < NN) {          // family 1: (kx,ky) = (k*m mod 512, k)
        int kx1 = (p * m1) & 511, kx2 = (p * m2) & 511;
        const int d1 = (64 * m1) & 511, d2 = (64 * m2) & 511;
#pragma unroll
        for (int i = 0; i < 4; i++) {
            const int k = p + 64 * i;
            const float2 s1 = fetch(A2, kx1, k);
            const float2 s2 = fetch(A2, kx2, k);
            buf[swz(k)] = make_float2(s1.x - s2.y, s1.y + s2.x);
            if (k > 0)      // mirror: Z[512-k] = conj(s1)+i*conj(s2)
                buf[swz(512 - k)] = make_float2(s1.x + s2.y, s2.x - s1.y);
            kx1 = (kx1 + d1) & 511;
            kx2 = (kx2 + d2) & 511;
        }
        if (p == 0) {
            const float2 s1 = fetch(A2, (256 * m1) & 511, 256);
            const float2 s2 = fetch(A2, (256 * m2) & 511, 256);
            buf[swz(256)] = make_float2(s1.x - s2.y, s1.y + s2.x);
        }
    } else {                // family 2: (kx,ky) = (k, 2k(m-512) mod 512), kx<=256
        const int t1 = m1 - NN, t2 = m2 - NN;
        int ky1 = (2 * p * t1) & 511, ky2 = (2 * p * t2) & 511;
        const int e1 = (128 * t1) & 511, e2 = (128 * t2) & 511;
#pragma unroll
        for (int i = 0; i < 4; i++) {
            const int k = p + 64 * i;
            const float2 s1 = A2[k * NN + ky1];
            const float2 s2 = A2[k * NN + ky2];
            buf[swz(k)] = make_float2(s1.x - s2.y, s1.y + s2.x);
            if (k > 0)
                buf[swz(512 - k)] = make_float2(s1.x + s2.y, s2.x - s1.y);
            ky1 = (ky1 + e1) & 511;
            ky2 = (ky2 + e2) & 511;
        }
        if (p == 0) {
            const float2 s1 = A2[256 * NN + ((512 * t1) & 511)];
            const float2 s2 = A2[256 * NN + ((512 * t2) & 511)];
            buf[swz(256)] = make_float2(s1.x - s2.y, s1.y + s2.x);
        }
    }
    __syncthreads();
    run_fft<true>(buf, sW, p, 1 + (f >> 1));
    const float SC = 8.6316745750242931e-5f;    // 1 / 512^1.5
    float2* o1 = (float2*)out + ((size_t)b * MU + m1) * NN;
    float2* o2 = (float2*)out + ((size_t)b * MU + m2) * NN;
#pragma unroll
    for (int s = p; s < 512; s += 64) {
        const float2 v = buf[swz(s)];
        __stcs(&o1[s], make_float2(v.x * SC, 0.0f));
        __stcs(&o2[s], make_float2(v.y * SC, 0.0f));
    }
}

extern "C" void kernel_launch(void* const* d_in, const int* in_sizes, int n_in,
                              void* d_out, int out_size) {
    const float* img = (const float*)d_in[0];
    float* out = (float*)d_out;

    twiddle_init<<<1, 64>>>();
    fft_rows<<<dim3(NN / 8, NB), 256>>>(img);
    fft_cols<<<dim3(65, NB), 256>>>();          // kx 0..259, guarded at 256
    gather_ifft<<<dim3(MU / 8, NB), 256>>>(out);
}

// round 16
// speedup vs baseline: 1.0387x; 1.0375x over previous
#include <cuda_runtime.h>

#define NN 512
#define NB 16
#define MU 768
#define KXD 257                       // stored kx range [0,256]
#define A2STRIDE (KXD * 512 * 4)      // float2 per batch-group partition
#define BUFP 516                      // padded unit-buffer stride (bank offset 8/c)

__device__ float2 g_A1[NB * NN * NN];     // row-FFT, kx<=256 valid  [b][y][kx]
__device__ float2 g_A2[4 * A2STRIDE];     // A2G[g][kx][ky][c], b = 4g+c
__device__ float2 g_W[64];                // twiddles e^{-2pi i r/512}, r<64

__device__ __forceinline__ float2 cadd(float2 a, float2 b) { return make_float2(a.x + b.x, a.y + b.y); }
__device__ __forceinline__ float2 csub(float2 a, float2 b) { return make_float2(a.x - b.x, a.y - b.y); }
__device__ __forceinline__ float2 cmul(float2 a, float2 b) {
    return make_float2(a.x * b.x - a.y * b.y, a.x * b.y + a.y * b.x);
}

// bank-conflict-killing swizzle: XOR bits[4:6] into bits[1:3] (involution)
__device__ __forceinline__ int swz(int i) { return i ^ (((i >> 4) & 7) << 1); }

// barrier shared by a PAIR of 64-thread FFT units (128 threads), id in {1,2}
__device__ __forceinline__ void bar128(int id) {
    asm volatile("bar.sync %0, 128;" :: "r"(id) : "memory");
}

template <bool CONJ>
__device__ __forceinline__ void dft8(const float2 a[8], float2 b[8]) {
    const float C = 0.70710678118654752f;
    float2 u0 = cadd(a[0], a[4]), u1 = cadd(a[1], a[5]);
    float2 u2 = cadd(a[2], a[6]), u3 = cadd(a[3], a[7]);
    float2 v0 = csub(a[0], a[4]);
    float2 d1 = csub(a[1], a[5]);
    float2 d2 = csub(a[2], a[6]);
    float2 d3 = csub(a[3], a[7]);
    float2 v1, v2, v3;
    if (!CONJ) {
        v1 = make_float2(C * (d1.x + d1.y), C * (d1.y - d1.x));
        v2 = make_float2(d2.y, -d2.x);
        v3 = make_float2(C * (d3.y - d3.x), -C * (d3.x + d3.y));
    } else {
        v1 = make_float2(C * (d1.x - d1.y), C * (d1.x + d1.y));
        v2 = make_float2(-d2.y, d2.x);
        v3 = make_float2(-C * (d3.x + d3.y), C * (d3.x - d3.y));
    }
    {
        float2 x0 = cadd(u0, u2), x1 = cadd(u1, u3);
        float2 y0 = csub(u0, u2);
        float2 t = csub(u1, u3);
        float2 y1 = (!CONJ) ? make_float2(t.y, -t.x) : make_float2(-t.y, t.x);
        b[0] = cadd(x0, x1); b[4] = csub(x0, x1);
        b[2] = cadd(y0, y1); b[6] = csub(y0, y1);
    }
    {
        float2 x0 = cadd(v0, v2), x1 = cadd(v1, v3);
        float2 y0 = csub(v0, v2);
        float2 t = csub(v1, v3);
        float2 y1 = (!CONJ) ? make_float2(t.y, -t.x) : make_float2(-t.y, t.x);
        b[1] = cadd(x0, x1); b[5] = csub(x0, x1);
        b[3] = cadd(y0, y1); b[7] = csub(y0, y1);
    }
}

// In-place radix-8 Stockham stage: read to regs, bar, write permuted, bar.
template <bool CONJ, int M>
__device__ __forceinline__ void stage_ip(float2* buf, const float2* W, int p,
                                         int bid) {
    float2 a[8];
#pragma unroll
    for (int r = 0; r < 8; r++) a[r] = buf[swz(p + 64 * r)];
    bar128(bid);
    float2 b[8];
    dft8<CONJ>(a, b);
    if (M == 64) {
#pragma unroll
        for (int q = 0; q < 8; q++) buf[swz(p + 64 * q)] = b[q];
    } else {
        const int k = p & (M - 1);
        const int jm = p - k;              // always < 64
        float2 w1 = W[jm];
        if (CONJ) w1.y = -w1.y;
        float2 w2 = cmul(w1, w1);
        float2 w3 = cmul(w2, w1);
        float2 w4 = cmul(w2, w2);
        float2 w5 = cmul(w4, w1);
        float2 w6 = cmul(w4, w2);
        float2 w7 = cmul(w4, w3);
        const int base = 8 * jm + k;
        buf[swz(base)]         = b[0];
        buf[swz(base + M)]     = cmul(b[1], w1);
        buf[swz(base + 2 * M)] = cmul(b[2], w2);
        buf[swz(base + 3 * M)] = cmul(b[3], w3);
        buf[swz(base + 4 * M)] = cmul(b[4], w4);
        buf[swz(base + 5 * M)] = cmul(b[5], w5);
        buf[swz(base + 6 * M)] = cmul(b[6], w6);
        buf[swz(base + 7 * M)] = cmul(b[7], w7);
    }
    bar128(bid);
}

template <bool CONJ>
__device__ __forceinline__ void run_fft(float2* buf, const float2* W, int p,
                                        int bid) {
    stage_ip<CONJ, 1>(buf, W, p, bid);
    stage_ip<CONJ, 8>(buf, W, p, bid);
    stage_ip<CONJ, 64>(buf, W, p, bid);
}

__global__ void twiddle_init() {
    const int r = threadIdx.x;
    float s, c;
    sincosf(-6.283185307179586f * (float)r * (1.0f / 512.0f), &s, &c);
    g_W[r] = make_float2(c, s);
}

__device__ __forceinline__ void load_tw(float2* sW, int tid) {
    if (tid < 64) sW[tid] = g_W[tid];
}

// Stage A: forward FFT along x for PAIRS of real rows (Z = rowA + i*rowB).
// 4 units = 8 rows per CTA. Store only kx in [0,256] of A1 [b][y][kx].
__global__ __launch_bounds__(256, 5) void fft_rows(const float* __restrict__ img) {
    __shared__ float2 sA[4 * 512], sW[64];
    const int tid = threadIdx.x, f = tid >> 6, p = tid & 63;
    const int y0 = blockIdx.x * 8, b = blockIdx.y;
    load_tw(sW, tid);
    const float* src = img + ((size_t)b * NN + y0) * NN;
    for (int i = tid; i < 4 * 512; i += 256) {
        const int ff = i >> 9, x = i & 511;
        sA[ff * 512 + swz(x)] =
            make_float2(__ldcs(&src[(2 * ff) * NN + x]),
                        __ldcs(&src[(2 * ff + 1) * NN + x]));
    }
    __syncthreads();
    float2* buf = sA + f * 512;
    run_fft<false>(buf, sW, p, 1 + (f >> 1));
    float2* dst = g_A1 + ((size_t)b * NN + y0) * NN;
#pragma unroll
    for (int k = p; k < 257; k += 64) {
        const float2 Zr = buf[swz(k)];
        const float2 Zs = buf[swz((512 - k) & 511)];
        dst[(2 * f) * NN + k] =
            make_float2(0.5f * (Zr.x + Zs.x), 0.5f * (Zr.y - Zs.y));
        dst[(2 * f + 1) * NN + k] =
            make_float2(0.5f * (Zr.y + Zs.y), 0.5f * (Zs.x - Zr.x));
    }
}

// Stage B: forward FFT along y for kx in [0,256]; store batch-interleaved
// A2G[g][kx][ky][c] with b = 4g+c.
__global__ __launch_bounds__(256, 5) void fft_cols() {
    __shared__ float2 sA[4 * 512], sW[64];
    const int tid = threadIdx.x, f = tid >> 6, p = tid & 63;
    const int kx0 = blockIdx.x * 4, b = blockIdx.y;
    load_tw(sW, tid);
    const float2* src = g_A1 + (size_t)b * NN * NN;
    for (int i = tid; i < 4 * 512; i += 256) {
        const int c = i & 3, y = i >> 2;
        sA[c * 512 + swz(y)] = src[(size_t)y * NN + kx0 + c];
    }
    __syncthreads();
    float2* buf = sA + f * 512;
    run_fft<false>(buf, sW, p, 1 + (f >> 1));
    const int kx = kx0 + f;
    if (kx <= 256) {
        float2* dst = g_A2 + (size_t)(b >> 2) * A2STRIDE + (b & 3);
#pragma unroll
        for (int ky = p; ky < 512; ky += 64)
            dst[(kx * 512 + ky) * 4] = buf[swz(ky)];
    }
}

// Fetch A2G element (batch-member c) with Hermitian mirror for kx > 256.
__device__ __forceinline__ float2 fetchG(const float2* A2G, int kx, int ky, int c) {
    if (kx <= 256) return A2G[(kx * 512 + ky) * 4 + c];
    const float2 v = A2G[((512 - kx) * 512 + ((512 - ky) & 511)) * 4 + c];
    return make_float2(v.x, -v.y);
}

// Stage C: CTA = (line pair, batch group). Cooperative coalesced gather:
// thread (c=tid&3, k0=tid>>2) loads k for batch 4g+c -> 32B/quad sectors.
// Slices Hermitian: gather k<=256, mirror-fill. Unit f iFFTs batch 4g+f.
__global__ __launch_bounds__(256, 5) void gather_ifft(float* __restrict__ out) {
    __shared__ float2 sA[4 * BUFP], sW[64];
    const int tid = threadIdx.x, f = tid >> 6, p = tid & 63;
    const int pair = blockIdx.x, g = blockIdx.y;
    const int m1 = 2 * pair, m2 = m1 + 1;
    load_tw(sW, tid);
    const float2* A2G = g_A2 + (size_t)g * A2STRIDE;
    const int c = tid & 3, k0 = tid >> 2;      // k0 in [0,64)
    float2* bufc = sA + c * BUFP;

    if (m1 < NN) {          // family 1: (kx,ky) = (k*m mod 512, k)
        int kx1 = (k0 * m1) & 511, kx2 = (k0 * m2) & 511;
        const int d1 = (64 * m1) & 511, d2 = (64 * m2) & 511;
#pragma unroll
        for (int i = 0; i < 4; i++) {
            const int k = k0 + 64 * i;
            const float2 s1 = fetchG(A2G, kx1, k, c);
            const float2 s2 = fetchG(A2G, kx2, k, c);
            bufc[swz(k)] = make_float2(s1.x - s2.y, s1.y + s2.x);
            if (k > 0)      // mirror: Z[512-k] = conj(s1)+i*conj(s2)
                bufc[swz(512 - k)] = make_float2(s1.x + s2.y, s2.x - s1.y);
            kx1 = (kx1 + d1) & 511;
            kx2 = (kx2 + d2) & 511;
        }
        if (k0 == 0) {      // k = 256
            const float2 s1 = fetchG(A2G, (256 * m1) & 511, 256, c);
            const float2 s2 = fetchG(A2G, (256 * m2) & 511, 256, c);
            bufc[swz(256)] = make_float2(s1.x - s2.y, s1.y + s2.x);
        }
    } else {                // family 2: (kx,ky) = (k, 2k(m-512) mod 512), kx<=256
        const int t1 = m1 - NN, t2 = m2 - NN;
        int ky1 = (2 * k0 * t1) & 511, ky2 = (2 * k0 * t2) & 511;
        const int e1 = (128 * t1) & 511, e2 = (128 * t2) & 511;
#pragma unroll
        for (int i = 0; i < 4; i++) {
            const int k = k0 + 64 * i;
            const float2 s1 = A2G[(k * 512 + ky1) * 4 + c];
            const float2 s2 = A2G[(k * 512 + ky2) * 4 + c];
            bufc[swz(k)] = make_float2(s1.x - s2.y, s1.y + s2.x);
            if (k > 0)
                bufc[swz(512 - k)] = make_float2(s1.x + s2.y, s2.x - s1.y);
            ky1 = (ky1 + e1) & 511;
            ky2 = (ky2 + e2) & 511;
        }
        if (k0 == 0) {      // k = 256
            const float2 s1 = A2G[(256 * 512 + ((512 * t1) & 511)) * 4 + c];
            const float2 s2 = A2G[(256 * 512 + ((512 * t2) & 511)) * 4 + c];
            bufc[swz(256)] = make_float2(s1.x - s2.y, s1.y + s2.x);
        }
    }
    __syncthreads();
    float2* buf = sA + f * BUFP;
    run_fft<true>(buf, sW, p, 1 + (f >> 1));
    const float SC = 8.6316745750242931e-5f;    // 1 / 512^1.5
    const int bg = 4 * g + f;
    float2* o1 = (float2*)out + ((size_t)bg * MU + m1) * NN;
    float2* o2 = (float2*)out + ((size_t)bg * MU + m2) * NN;
#pragma unroll
    for (int s = p; s < 512; s += 64) {
        const float2 v = buf[swz(s)];
        __stcs(&o1[s], make_float2(v.x * SC, 0.0f));
        __stcs(&o2[s], make_float2(v.y * SC, 0.0f));
    }
}

extern "C" void kernel_launch(void* const* d_in, const int* in_sizes, int n_in,
                              void* d_out, int out_size) {
    const float* img = (const float*)d_in[0];
    float* out = (float*)d_out;

    twiddle_init<<<1, 64>>>();
    fft_rows<<<dim3(NN / 8, NB), 256>>>(img);
    fft_cols<<<dim3(65, NB), 256>>>();          // kx 0..259, guarded at 256
    gather_ifft<<<dim3(MU / 2, 4), 256>>>(out); // 384 pairs x 4 batch-groups
}